// round 1
// baseline (speedup 1.0000x reference)
#include <cuda_runtime.h>

// ---------------------------------------------------------------------------
// ScaleSelfAttention: out = x + gamma * softmax((xWf)(xWg)^T) (xWh)
// B=4, H=W=64 (N=4096), C=256, d=32
// ---------------------------------------------------------------------------

#define BATCH 4
#define NTOK  4096
#define CDIM  256
#define DDIM  32

// device scratch for projections (f, g, h)
__device__ float g_f[BATCH * NTOK * DDIM];   // 2 MB
__device__ float g_g[BATCH * NTOK * DDIM];   // 2 MB
__device__ float g_h[BATCH * NTOK * CDIM];   // 16 MB

// ---------------------------------------------------------------------------
// Kernel 1: projections. One GEMM [16384 x 256] @ [256 x 320]
// (320 logical cols = 32 f | 32 g | 256 h). 64 rows per block, K chunked by 64.
// ---------------------------------------------------------------------------
__global__ __launch_bounds__(256) void proj_kernel(
    const float* __restrict__ x,
    const float* __restrict__ wf,
    const float* __restrict__ wg,
    const float* __restrict__ wh)
{
    __shared__ float sX[64 * 68];   // [row][k] padded stride 68
    __shared__ float sW[64 * 64];   // [k][col]

    const int t = threadIdx.x;
    const int rowBase = blockIdx.x * 64;
    const int rg = t >> 4;          // 0..15 -> rows rg*4..+3
    const int cg = t & 15;          // 0..15 -> cols cg*4..+3

    float acc[5][16];
#pragma unroll
    for (int cc = 0; cc < 5; cc++)
#pragma unroll
        for (int q = 0; q < 16; q++) acc[cc][q] = 0.f;

    for (int kc = 0; kc < 4; kc++) {
        __syncthreads();
        // load x chunk [64 rows x 64 k]
        for (int idx = t; idx < 4096; idx += 256) {
            int r = idx >> 6, kk = idx & 63;
            sX[r * 68 + kk] = x[(rowBase + r) * 256 + kc * 64 + kk];
        }
#pragma unroll
        for (int cc = 0; cc < 5; cc++) {
            __syncthreads();
            // load weight chunk [64 k x 64 cols]
            for (int idx = t; idx < 4096; idx += 256) {
                int kk = idx >> 6, j = idx & 63;
                int kglob = kc * 64 + kk;
                int c = cc * 64 + j;
                float w;
                if (c < 32)       w = wf[kglob * 32 + c];
                else if (c < 64)  w = wg[kglob * 32 + (c - 32)];
                else              w = wh[kglob * 256 + (c - 64)];
                sW[kk * 64 + j] = w;
            }
            __syncthreads();
#pragma unroll 4
            for (int kk = 0; kk < 64; kk++) {
                float a[4], bv[4];
#pragma unroll
                for (int i = 0; i < 4; i++) a[i] = sX[(rg * 4 + i) * 68 + kk];
#pragma unroll
                for (int j = 0; j < 4; j++) bv[j] = sW[kk * 64 + cg * 4 + j];
#pragma unroll
                for (int i = 0; i < 4; i++)
#pragma unroll
                    for (int j = 0; j < 4; j++)
                        acc[cc][i * 4 + j] += a[i] * bv[j];
            }
        }
    }

    // store to scratch
#pragma unroll
    for (int cc = 0; cc < 5; cc++) {
#pragma unroll
        for (int i = 0; i < 4; i++) {
            int row = rowBase + rg * 4 + i;
#pragma unroll
            for (int j = 0; j < 4; j++) {
                int c = cc * 64 + cg * 4 + j;
                float v = acc[cc][i * 4 + j];
                if (c < 32)       g_f[row * 32 + c] = v;
                else if (c < 64)  g_g[row * 32 + (c - 32)] = v;
                else              g_h[row * 256 + (c - 64)] = v;
            }
        }
    }
}

// ---------------------------------------------------------------------------
// Kernel 2: flash attention + residual epilogue.
// Grid (64 q-tiles, 4 batches). 256 threads. 64 queries x 64 keys per step.
// ---------------------------------------------------------------------------
#define SS_STRIDE 68
#define SF_STRIDE 33
// smem floats: sH 16384 | sS 64*68 | sF 64*33 | sG 64*33 | m,l,a 192
#define SMEM2_FLOATS (16384 + 64 * 68 + 64 * 33 + 64 * 33 + 192)
#define SMEM2_BYTES (SMEM2_FLOATS * 4)

__global__ __launch_bounds__(256, 2) void attn_kernel(
    const float* __restrict__ x,
    const float* __restrict__ gamma_p,
    float* __restrict__ out)
{
    extern __shared__ float sm[];
    float* sH = sm;                        // [64][256]
    float* sS = sm + 16384;                // [64][68]
    float* sF = sS + 64 * SS_STRIDE;       // [64][33]
    float* sG = sF + 64 * SF_STRIDE;       // [64][33]
    float* sM = sG + 64 * SF_STRIDE;       // [64]
    float* sL = sM + 64;                   // [64]
    float* sA = sL + 64;                   // [64]

    const int t = threadIdx.x;
    const int qBase = blockIdx.x * 64;
    const int b = blockIdx.y;
    const float* fB = g_f + b * NTOK * DDIM;
    const float* gB = g_g + b * NTOK * DDIM;
    const float* hB = g_h + (size_t)b * NTOK * CDIM;

    const int rg = t >> 5;     // phase B: warp -> rows rg*8..+7
    const int cg = t & 31;     // phase B: cols cg*8..+7
    const int rgA = t >> 4;    // phase A: rows rgA*4..+3
    const int cgA = t & 15;    // phase A: cols cgA*4..+3
    const int lane = t & 31;

    // load query projections once
    for (int idx = t; idx < 64 * 32; idx += 256) {
        int r = idx >> 5, k = idx & 31;
        sF[r * SF_STRIDE + k] = fB[(qBase + r) * 32 + k];
    }
    if (t < 64) { sM[t] = -1e30f; sL[t] = 0.f; }

    float O[64];
#pragma unroll
    for (int q = 0; q < 64; q++) O[q] = 0.f;

    for (int kt = 0; kt < 64; kt++) {
        __syncthreads();
        const int kBase = kt * 64;
        // load key projections and values
        for (int idx = t; idx < 64 * 32; idx += 256) {
            int r = idx >> 5, k = idx & 31;
            sG[r * SF_STRIDE + k] = gB[(kBase + r) * 32 + k];
        }
        {
            const float4* hsrc = (const float4*)(hB + (size_t)kBase * 256);
            float4* hdst = (float4*)sH;
            for (int idx = t; idx < 4096; idx += 256)
                hdst[idx] = hsrc[idx];
        }
        __syncthreads();

        // ---- Phase A: S[64][64] = F . G^T (K=32) ----
        {
            float s[16];
#pragma unroll
            for (int q = 0; q < 16; q++) s[q] = 0.f;
#pragma unroll
            for (int k = 0; k < 32; k++) {
                float a[4], bv[4];
#pragma unroll
                for (int i = 0; i < 4; i++) a[i] = sF[(rgA * 4 + i) * SF_STRIDE + k];
#pragma unroll
                for (int j = 0; j < 4; j++) bv[j] = sG[(cgA * 4 + j) * SF_STRIDE + k];
#pragma unroll
                for (int i = 0; i < 4; i++)
#pragma unroll
                    for (int j = 0; j < 4; j++)
                        s[i * 4 + j] += a[i] * bv[j];
            }
#pragma unroll
            for (int i = 0; i < 4; i++)
#pragma unroll
                for (int j = 0; j < 4; j++)
                    sS[(rgA * 4 + i) * SS_STRIDE + cgA * 4 + j] = s[i * 4 + j];
        }
        __syncthreads();

        // ---- Online softmax: warp rg owns rows rg*8..+7 ----
        for (int rr = 0; rr < 8; rr++) {
            int r = rg * 8 + rr;
            float s0 = sS[r * SS_STRIDE + lane];
            float s1 = sS[r * SS_STRIDE + lane + 32];
            float mx = fmaxf(s0, s1);
#pragma unroll
            for (int o = 16; o > 0; o >>= 1)
                mx = fmaxf(mx, __shfl_xor_sync(0xffffffff, mx, o));
            float mold = sM[r];
            float mnew = fmaxf(mold, mx);
            float p0 = __expf(s0 - mnew);
            float p1 = __expf(s1 - mnew);
            sS[r * SS_STRIDE + lane] = p0;
            sS[r * SS_STRIDE + lane + 32] = p1;
            float sum = p0 + p1;
#pragma unroll
            for (int o = 16; o > 0; o >>= 1)
                sum += __shfl_xor_sync(0xffffffff, sum, o);
            if (lane == 0) {
                float alpha = __expf(mold - mnew);
                sL[r] = sL[r] * alpha + sum;
                sM[r] = mnew;
                sA[r] = alpha;
            }
        }
        __syncthreads();

        // ---- Phase B: O[64x256] += P[64x64] . H[64x256] ----
        float al[8];
#pragma unroll
        for (int i = 0; i < 8; i++) al[i] = sA[rg * 8 + i];
#pragma unroll
        for (int i = 0; i < 8; i++)
#pragma unroll
            for (int j = 0; j < 8; j++)
                O[i * 8 + j] *= al[i];

#pragma unroll 2
        for (int kk = 0; kk < 64; kk++) {
            float p[8];
#pragma unroll
            for (int i = 0; i < 8; i++) p[i] = sS[(rg * 8 + i) * SS_STRIDE + kk];
            float4 h0 = *(const float4*)&sH[kk * 256 + cg * 8];
            float4 h1 = *(const float4*)&sH[kk * 256 + cg * 8 + 4];
#pragma unroll
            for (int i = 0; i < 8; i++) {
                O[i * 8 + 0] += p[i] * h0.x;
                O[i * 8 + 1] += p[i] * h0.y;
                O[i * 8 + 2] += p[i] * h0.z;
                O[i * 8 + 3] += p[i] * h0.w;
                O[i * 8 + 4] += p[i] * h1.x;
                O[i * 8 + 5] += p[i] * h1.y;
                O[i * 8 + 6] += p[i] * h1.z;
                O[i * 8 + 7] += p[i] * h1.w;
            }
        }
    }
    __syncthreads();

    // ---- Epilogue: out = x + gamma * O / l ----
    const float gamma = *gamma_p;
#pragma unroll
    for (int i = 0; i < 8; i++) {
        int row = b * NTOK + qBase + rg * 8 + i;
        float linv = 1.f / sL[rg * 8 + i];
        size_t base = (size_t)row * 256 + cg * 8;
        float4 x0 = *(const float4*)&x[base];
        float4 x1 = *(const float4*)&x[base + 4];
        float4 o0, o1;
        o0.x = x0.x + gamma * O[i * 8 + 0] * linv;
        o0.y = x0.y + gamma * O[i * 8 + 1] * linv;
        o0.z = x0.z + gamma * O[i * 8 + 2] * linv;
        o0.w = x0.w + gamma * O[i * 8 + 3] * linv;
        o1.x = x1.x + gamma * O[i * 8 + 4] * linv;
        o1.y = x1.y + gamma * O[i * 8 + 5] * linv;
        o1.z = x1.z + gamma * O[i * 8 + 6] * linv;
        o1.w = x1.w + gamma * O[i * 8 + 7] * linv;
        *(float4*)&out[base] = o0;
        *(float4*)&out[base + 4] = o1;
    }
}

// ---------------------------------------------------------------------------
extern "C" void kernel_launch(void* const* d_in, const int* in_sizes, int n_in,
                              void* d_out, int out_size)
{
    const float* x  = (const float*)d_in[0];
    const float* wf = (const float*)d_in[1];
    const float* wg = (const float*)d_in[2];
    const float* wh = (const float*)d_in[3];
    const float* gm = (const float*)d_in[4];
    float* out = (float*)d_out;

    cudaFuncSetAttribute(attn_kernel,
                         cudaFuncAttributeMaxDynamicSharedMemorySize,
                         SMEM2_BYTES);

    proj_kernel<<<256, 256>>>(x, wf, wg, wh);
    attn_kernel<<<dim3(64, 4), 256, SMEM2_BYTES>>>(x, gm, out);
}

// round 3
// speedup vs baseline: 3.3731x; 3.3731x over previous
#include <cuda_runtime.h>
#include <cuda_bf16.h>
#include <cstdint>

// ---------------------------------------------------------------------------
// ScaleSelfAttention: out = x + gamma * softmax((xWf)(xWg)^T) (xWh)
// B=4, N=4096, C=256, d=32
//   proj_kernel : f,g fp32 transposed [b][k][tok]; h -> bf16 transposed
//                 [b][c][tok]; ||f_row||^2; per-batch max ||g||^2
//   attn_kernel : 64 queries/CTA. S = F.G^T fp32 on FFMA,
//                 P = exp(S - mhat), mhat = ||f||*max||g|| (upper bound =>
//                 single pass, no rescale). O += P.H via mma.sync bf16
//                 (register accumulators). Epilogue fuses x + gamma*O/l.
// ---------------------------------------------------------------------------

#define BATCH 4
#define NTOK  4096
#define CDIM  256
#define DDIM  32

__device__ float         g_ft[BATCH * DDIM * NTOK];
__device__ float         g_gt[BATCH * DDIM * NTOK];
__device__ __nv_bfloat16 g_ht[BATCH * CDIM * NTOK];
__device__ float         g_fn2[BATCH * NTOK];
__device__ int           g_gmax2[BATCH];

__global__ void init_kernel() {
    if (threadIdx.x < BATCH) g_gmax2[threadIdx.x] = 0;
}

// ---------------------------------------------------------------------------
// Projections: [16384 x 256] @ [256 x 320], 64 rows/block, K chunked by 64.
// ---------------------------------------------------------------------------
__global__ __launch_bounds__(256) void proj_kernel(
    const float* __restrict__ x,
    const float* __restrict__ wf,
    const float* __restrict__ wg,
    const float* __restrict__ wh)
{
    __shared__ float sX[64 * 65];
    __shared__ float sW[64 * 64];

    const int t = threadIdx.x;
    const int rowBase = blockIdx.x * 64;
    const int bb = rowBase >> 12;
    const int tokBase = rowBase & 4095;
    const int rg = t >> 4;
    const int cg = t & 15;

    float acc[5][16];
#pragma unroll
    for (int cc = 0; cc < 5; cc++)
#pragma unroll
        for (int q = 0; q < 16; q++) acc[cc][q] = 0.f;

    for (int kc = 0; kc < 4; kc++) {
        __syncthreads();
        for (int idx = t; idx < 4096; idx += 256) {
            int r = idx >> 6, kk = idx & 63;
            sX[r * 65 + kk] = x[(rowBase + r) * 256 + kc * 64 + kk];
        }
#pragma unroll
        for (int cc = 0; cc < 5; cc++) {
            __syncthreads();
            for (int idx = t; idx < 4096; idx += 256) {
                int kk = idx >> 6, j = idx & 63;
                int kglob = kc * 64 + kk;
                int c = cc * 64 + j;
                float w;
                if (c < 32)       w = wf[kglob * 32 + c];
                else if (c < 64)  w = wg[kglob * 32 + (c - 32)];
                else              w = wh[kglob * 256 + (c - 64)];
                sW[kk * 64 + j] = w;
            }
            __syncthreads();
#pragma unroll 4
            for (int kk = 0; kk < 64; kk++) {
                float a[4], bv[4];
#pragma unroll
                for (int i = 0; i < 4; i++) a[i] = sX[(rg * 4 + i) * 65 + kk];
#pragma unroll
                for (int j = 0; j < 4; j++) bv[j] = sW[kk * 64 + cg * 4 + j];
#pragma unroll
                for (int i = 0; i < 4; i++)
#pragma unroll
                    for (int j = 0; j < 4; j++)
                        acc[cc][i * 4 + j] += a[i] * bv[j];
            }
        }
    }

#pragma unroll
    for (int cc = 0; cc < 5; cc++) {
        __syncthreads();
#pragma unroll
        for (int i = 0; i < 4; i++)
#pragma unroll
            for (int j = 0; j < 4; j++)
                sX[(rg * 4 + i) * 65 + cg * 4 + j] = acc[cc][i * 4 + j];
        __syncthreads();

        if (cc == 0) {
            if (t < 64) {
                float f2 = 0.f, g2 = 0.f;
#pragma unroll 8
                for (int k = 0; k < 32; k++) {
                    float v = sX[t * 65 + k];      f2 += v * v;
                    float w = sX[t * 65 + 32 + k]; g2 += w * w;
                }
                g_fn2[rowBase + t] = f2;
                atomicMax(&g_gmax2[bb], __float_as_int(g2));
            }
            for (int idx = t; idx < 4096; idx += 256) {
                int c = idx >> 6, tok = idx & 63;
                float v = sX[tok * 65 + c];
                if (c < 32) g_ft[(bb * 32 + c) * 4096 + tokBase + tok] = v;
                else        g_gt[(bb * 32 + (c - 32)) * 4096 + tokBase + tok] = v;
            }
        } else {
            for (int idx = t; idx < 4096; idx += 256) {
                int c = idx >> 6, tok = idx & 63;
                float v = sX[tok * 65 + c];
                g_ht[(size_t)(bb * 256 + (cc - 1) * 64 + c) * 4096 + tokBase + tok] =
                    __float2bfloat16(v);
            }
        }
    }
}

// ---------------------------------------------------------------------------
// Attention kernel: mma.sync bf16, register accumulators
// ---------------------------------------------------------------------------
#define HS_STRIDE 176                       // bytes/row, conflict-free, 16B-aligned
#define PB_STRIDE 176
#define FT_STRIDE 68                        // floats/row (272B, 16B-aligned)
#define HS_OFF 0
#define PB_OFF (256 * HS_STRIDE)            // 45056
#define FT_OFF (PB_OFF + 64 * PB_STRIDE)    // 56320
#define GT_OFF (FT_OFF + 32 * FT_STRIDE * 4)// 65024
#define GT_BUF (32 * FT_STRIDE * 4)         // 8704
#define SL_OFF (GT_OFF + 2 * GT_BUF)        // 82432
#define SM_BYTES (SL_OFF + 256)             // 82688

__device__ __forceinline__ uint32_t smem_u32(const void* p) {
    uint32_t a;
    asm("{ .reg .u64 t; cvta.to.shared.u64 t, %1; cvt.u32.u64 %0, t; }"
        : "=r"(a) : "l"(p));
    return a;
}

__device__ __forceinline__ void cp_async16(uint32_t dst, const void* src) {
    asm volatile("cp.async.cg.shared.global [%0], [%1], 16;"
                 :: "r"(dst), "l"(src) : "memory");
}

__device__ __forceinline__ void mma16816(float* d, const uint32_t* a,
                                         const uint32_t* bv) {
    asm volatile(
        "mma.sync.aligned.m16n8k16.row.col.f32.bf16.bf16.f32 "
        "{%0,%1,%2,%3}, {%4,%5,%6,%7}, {%8,%9}, {%0,%1,%2,%3};"
        : "+f"(d[0]), "+f"(d[1]), "+f"(d[2]), "+f"(d[3])
        : "r"(a[0]), "r"(a[1]), "r"(a[2]), "r"(a[3]), "r"(bv[0]), "r"(bv[1]));
}

__global__ __launch_bounds__(256, 2) void attn_kernel(
    const float* __restrict__ x,
    const float* __restrict__ gamma_p,
    float* __restrict__ out)
{
    extern __shared__ char sm[];
    const int t = threadIdx.x;
    const int lane = t & 31;
    const int wid = t >> 5;
    const int gid = lane >> 2;      // mma group id
    const int tig = lane & 3;       // thread in group
    const int b = blockIdx.y;
    const int qBase = blockIdx.x * 64;
    const int rgA = t >> 4;         // S-phase rows rgA*4..+3
    const int cgA = t & 15;         // S-phase cols cgA*4..+3

    float* sFt = (float*)(sm + FT_OFF);
    float* sL  = (float*)(sm + SL_OFF);
    const uint32_t smbase = smem_u32(sm);

    // prologue: F^T (whole CTA, fp32) and G^T tile 0
    for (int idx = t; idx < 2048; idx += 256) {
        int k = idx >> 6, tok = idx & 63;
        sFt[k * FT_STRIDE + tok] = g_ft[(b * 32 + k) * 4096 + qBase + tok];
        ((float*)(sm + GT_OFF))[k * FT_STRIDE + tok] =
            g_gt[(b * 32 + k) * 4096 + tok];
    }
    if (t < 64) sL[t] = 0.f;

    const float gms = sqrtf(__int_as_float(g_gmax2[b]));
    float mh[4];
#pragma unroll
    for (int i = 0; i < 4; i++)
        mh[i] = sqrtf(g_fn2[b * 4096 + qBase + rgA * 4 + i]) * gms;

    float acc[16][4];
#pragma unroll
    for (int j = 0; j < 16; j++)
#pragma unroll
        for (int q = 0; q < 4; q++) acc[j][q] = 0.f;

    const int qoff = (wid & 3) * 16;
    const int coff = (wid >> 2) * 128;

    for (int kt = 0; kt < 64; kt++) {
        __syncthreads();    // prev MMA done with Pb/Hs; prev S done with sGt

        // async fill H^T tile [256 c][64 key] bf16
#pragma unroll
        for (int it = 0; it < 8; it++) {
            int idx = t + it * 256;
            int ch = idx >> 3, part = idx & 7;
            uint32_t dst = smbase + HS_OFF + ch * HS_STRIDE + part * 16;
            const __nv_bfloat16* src =
                g_ht + (size_t)(b * 256 + ch) * 4096 + kt * 64 + part * 8;
            cp_async16(dst, src);
        }
        // async prefetch next G^T tile
        if (kt < 63) {
#pragma unroll
            for (int it = 0; it < 2; it++) {
                int idx = t + it * 256;
                int k = idx >> 4, chunk = idx & 15;
                uint32_t dst = smbase + GT_OFF + ((kt + 1) & 1) * GT_BUF +
                               k * (FT_STRIDE * 4) + chunk * 16;
                const float* src =
                    g_gt + (size_t)(b * 32 + k) * 4096 + (kt + 1) * 64 + chunk * 4;
                cp_async16(dst, src);
            }
        }
        asm volatile("cp.async.commit_group;" ::: "memory");

        // ---- S = F.G^T fp32 ; P = exp(S - mhat) ----
        const float* sG = (const float*)(sm + GT_OFF + (kt & 1) * GT_BUF);
        float p[4][4];
#pragma unroll
        for (int i = 0; i < 4; i++)
#pragma unroll
            for (int j = 0; j < 4; j++) p[i][j] = 0.f;

#pragma unroll 8
        for (int kk = 0; kk < 32; kk++) {
            float4 f4 = *(const float4*)&sFt[kk * FT_STRIDE + rgA * 4];
            float4 g4 = *(const float4*)&sG[kk * FT_STRIDE + cgA * 4];
            float fa[4] = {f4.x, f4.y, f4.z, f4.w};
            float ga[4] = {g4.x, g4.y, g4.z, g4.w};
#pragma unroll
            for (int i = 0; i < 4; i++)
#pragma unroll
                for (int j = 0; j < 4; j++)
                    p[i][j] += fa[i] * ga[j];
        }

        float rs[4];
#pragma unroll
        for (int i = 0; i < 4; i++) {
            p[i][0] = __expf(p[i][0] - mh[i]);
            p[i][1] = __expf(p[i][1] - mh[i]);
            p[i][2] = __expf(p[i][2] - mh[i]);
            p[i][3] = __expf(p[i][3] - mh[i]);
            rs[i] = (p[i][0] + p[i][1]) + (p[i][2] + p[i][3]);
        }
#pragma unroll
        for (int off = 1; off < 16; off <<= 1)
#pragma unroll
            for (int i = 0; i < 4; i++)
                rs[i] += __shfl_xor_sync(0xffffffffu, rs[i], off);
        if (cgA == 0) {
#pragma unroll
            for (int i = 0; i < 4; i++) sL[rgA * 4 + i] += rs[i];
        }

        // store P bf16 [64 q][64 key]
#pragma unroll
        for (int i = 0; i < 4; i++) {
            __nv_bfloat162 lo = __floats2bfloat162_rn(p[i][0], p[i][1]);
            __nv_bfloat162 hi = __floats2bfloat162_rn(p[i][2], p[i][3]);
            uint2 v;
            v.x = *(uint32_t*)&lo;
            v.y = *(uint32_t*)&hi;
            *(uint2*)(sm + PB_OFF + (rgA * 4 + i) * PB_STRIDE + cgA * 8) = v;
        }

        asm volatile("cp.async.wait_group 0;" ::: "memory");
        __syncthreads();    // P + H + next G visible

        // ---- MMA: warp slab 16q x 128c, 64 keys ----
        uint32_t a[4][4];
        const char* Pw = sm + PB_OFF + (qoff + gid) * PB_STRIDE + tig * 4;
#pragma unroll
        for (int s = 0; s < 4; s++) {
            a[s][0] = *(const uint32_t*)(Pw + s * 32);
            a[s][1] = *(const uint32_t*)(Pw + 8 * PB_STRIDE + s * 32);
            a[s][2] = *(const uint32_t*)(Pw + s * 32 + 16);
            a[s][3] = *(const uint32_t*)(Pw + 8 * PB_STRIDE + s * 32 + 16);
        }
        const char* Hw = sm + HS_OFF + (coff + gid) * HS_STRIDE + tig * 4;
#pragma unroll
        for (int j = 0; j < 16; j++) {
            const char* hb = Hw + j * 8 * HS_STRIDE;
            uint32_t bv[8];
#pragma unroll
            for (int s = 0; s < 4; s++) {
                bv[s * 2]     = *(const uint32_t*)(hb + s * 32);
                bv[s * 2 + 1] = *(const uint32_t*)(hb + s * 32 + 16);
            }
#pragma unroll
            for (int s = 0; s < 4; s++)
                mma16816(acc[j], a[s], &bv[s * 2]);
        }
    }
    __syncthreads();

    // ---- epilogue: out = x + gamma * O / l ----
    const float gamma = *gamma_p;
    const int r0 = qoff + gid;
    const int r1 = r0 + 8;
    const float gl0 = gamma / sL[r0];
    const float gl1 = gamma / sL[r1];
    const size_t gb0 = (size_t)(b * NTOK + qBase + r0) * CDIM + coff + tig * 2;
    const size_t gb1 = (size_t)(b * NTOK + qBase + r1) * CDIM + coff + tig * 2;

#pragma unroll
    for (int j = 0; j < 16; j++) {
        float2 xv0 = *(const float2*)&x[gb0 + j * 8];
        float2 xv1 = *(const float2*)&x[gb1 + j * 8];
        float2 o0, o1;
        o0.x = xv0.x + gl0 * acc[j][0];
        o0.y = xv0.y + gl0 * acc[j][1];
        o1.x = xv1.x + gl1 * acc[j][2];
        o1.y = xv1.y + gl1 * acc[j][3];
        *(float2*)&out[gb0 + j * 8] = o0;
        *(float2*)&out[gb1 + j * 8] = o1;
    }
}

// ---------------------------------------------------------------------------
extern "C" void kernel_launch(void* const* d_in, const int* in_sizes, int n_in,
                              void* d_out, int out_size)
{
    const float* x  = (const float*)d_in[0];
    const float* wf = (const float*)d_in[1];
    const float* wg = (const float*)d_in[2];
    const float* wh = (const float*)d_in[3];
    const float* gm = (const float*)d_in[4];
    float* out = (float*)d_out;

    cudaFuncSetAttribute(attn_kernel,
                         cudaFuncAttributeMaxDynamicSharedMemorySize,
                         SM_BYTES);

    init_kernel<<<1, 32>>>();
    proj_kernel<<<256, 256>>>(x, wf, wg, wh);
    attn_kernel<<<dim3(64, 4), 256, SM_BYTES>>>(x, gm, out);
}

// round 4
// speedup vs baseline: 3.5481x; 1.0519x over previous
#include <cuda_runtime.h>
#include <cuda_bf16.h>
#include <cstdint>

// ---------------------------------------------------------------------------
// ScaleSelfAttention: out = x + gamma * softmax((xWf)(xWg)^T) (xWh)
// B=4, N=4096, C=256, d=32
//   proj_kernel : f,g fp32 transposed; h bf16 transposed; ||f||^2; per-block
//                 max ||g||^2. Inner loop on packed fma.rn.f32x2.
//   attn_kernel : 64 q/CTA. S fp32 via f32x2 FFMA, P = exp(S - mhat) with
//                 mhat = ||f||*max||g|| (upper bound -> single pass, no
//                 rescale). O += P.H via mma.sync bf16, fragments via
//                 ldmatrix.x4. Epilogue fuses x + gamma*O/l.
// ---------------------------------------------------------------------------

#define BATCH 4
#define NTOK  4096
#define CDIM  256
#define DDIM  32

__device__ float         g_ft[BATCH * DDIM * NTOK];
__device__ float         g_gt[BATCH * DDIM * NTOK];
__device__ __nv_bfloat16 g_ht[BATCH * CDIM * NTOK];
__device__ float         g_fn2[BATCH * NTOK];
__device__ float         g_g2blk[256];          // per-proj-block max ||g||^2

typedef unsigned long long ull;

__device__ __forceinline__ void fma2(ull& d, ull a, ull b) {
    asm("fma.rn.f32x2 %0, %1, %2, %0;" : "+l"(d) : "l"(a), "l"(b));
}
__device__ __forceinline__ ull splat2(float v) {
    ull r;
    asm("mov.b64 %0, {%1, %1};" : "=l"(r) : "f"(v));
    return r;
}
__device__ __forceinline__ float2 unpack2(ull v) {
    float2 r;
    asm("mov.b64 {%0, %1}, %2;" : "=f"(r.x), "=f"(r.y) : "l"(v));
    return r;
}

// ---------------------------------------------------------------------------
// Projections: [16384 x 256] @ [256 x 320], 64 rows/block, K chunked by 64.
// ---------------------------------------------------------------------------
__global__ __launch_bounds__(256) void proj_kernel(
    const float* __restrict__ x,
    const float* __restrict__ wf,
    const float* __restrict__ wg,
    const float* __restrict__ wh)
{
    __shared__ float sX[64 * 65];
    __shared__ float sW[64 * 64];
    __shared__ float sGm[2];

    const int t = threadIdx.x;
    const int rowBase = blockIdx.x * 64;
    const int bb = rowBase >> 12;
    const int tokBase = rowBase & 4095;
    const int rg = t >> 4;
    const int cg = t & 15;

    ull acc[5][8];   // [cc][i*2 + jpair]
#pragma unroll
    for (int cc = 0; cc < 5; cc++)
#pragma unroll
        for (int q = 0; q < 8; q++) acc[cc][q] = 0ull;

    for (int kc = 0; kc < 4; kc++) {
        __syncthreads();
        for (int idx = t; idx < 4096; idx += 256) {
            int r = idx >> 6, kk = idx & 63;
            sX[r * 65 + kk] = x[(rowBase + r) * 256 + kc * 64 + kk];
        }
#pragma unroll
        for (int cc = 0; cc < 5; cc++) {
            __syncthreads();
            for (int idx = t; idx < 4096; idx += 256) {
                int kk = idx >> 6, j = idx & 63;
                int kglob = kc * 64 + kk;
                int c = cc * 64 + j;
                float w;
                if (c < 32)       w = wf[kglob * 32 + c];
                else if (c < 64)  w = wg[kglob * 32 + (c - 32)];
                else              w = wh[kglob * 256 + (c - 64)];
                sW[kk * 64 + j] = w;
            }
            __syncthreads();
#pragma unroll 4
            for (int kk = 0; kk < 64; kk++) {
                ulonglong2 bp = *(const ulonglong2*)&sW[kk * 64 + cg * 4];
                ull as[4];
#pragma unroll
                for (int i = 0; i < 4; i++)
                    as[i] = splat2(sX[(rg * 4 + i) * 65 + kk]);
#pragma unroll
                for (int i = 0; i < 4; i++) {
                    fma2(acc[cc][i * 2 + 0], as[i], bp.x);
                    fma2(acc[cc][i * 2 + 1], as[i], bp.y);
                }
            }
        }
    }

#pragma unroll
    for (int cc = 0; cc < 5; cc++) {
        __syncthreads();
#pragma unroll
        for (int i = 0; i < 4; i++) {
            float2 lo = unpack2(acc[cc][i * 2 + 0]);
            float2 hi = unpack2(acc[cc][i * 2 + 1]);
            sX[(rg * 4 + i) * 65 + cg * 4 + 0] = lo.x;
            sX[(rg * 4 + i) * 65 + cg * 4 + 1] = lo.y;
            sX[(rg * 4 + i) * 65 + cg * 4 + 2] = hi.x;
            sX[(rg * 4 + i) * 65 + cg * 4 + 3] = hi.y;
        }
        __syncthreads();

        if (cc == 0) {
            float g2 = 0.f;
            if (t < 64) {
                float f2 = 0.f;
#pragma unroll 8
                for (int k = 0; k < 32; k++) {
                    float v = sX[t * 65 + k];      f2 += v * v;
                    float w = sX[t * 65 + 32 + k]; g2 += w * w;
                }
                g_fn2[rowBase + t] = f2;
            }
            if (t < 64) {
#pragma unroll
                for (int o = 16; o > 0; o >>= 1)
                    g2 = fmaxf(g2, __shfl_xor_sync(0xffffffffu, g2, o));
                if ((t & 31) == 0) sGm[t >> 5] = g2;
            }
            for (int idx = t; idx < 4096; idx += 256) {
                int c = idx >> 6, tok = idx & 63;
                float v = sX[tok * 65 + c];
                if (c < 32) g_ft[(bb * 32 + c) * 4096 + tokBase + tok] = v;
                else        g_gt[(bb * 32 + (c - 32)) * 4096 + tokBase + tok] = v;
            }
        } else {
            for (int idx = t; idx < 4096; idx += 256) {
                int c = idx >> 6, tok = idx & 63;
                float v = sX[tok * 65 + c];
                g_ht[(size_t)(bb * 256 + (cc - 1) * 64 + c) * 4096 + tokBase + tok] =
                    __float2bfloat16(v);
            }
        }
    }
    __syncthreads();
    if (t == 0) g_g2blk[blockIdx.x] = fmaxf(sGm[0], sGm[1]);
}

// ---------------------------------------------------------------------------
// Attention kernel: mma.sync bf16 + ldmatrix, f32x2 S phase
// ---------------------------------------------------------------------------
#define HS_STRIDE 176
#define PB_STRIDE 176
#define FT_STRIDE 68
#define HS_OFF 0
#define PB_OFF (256 * HS_STRIDE)
#define FT_OFF (PB_OFF + 64 * PB_STRIDE)
#define GT_OFF (FT_OFF + 32 * FT_STRIDE * 4)
#define GT_BUF (32 * FT_STRIDE * 4)
#define SL_OFF (GT_OFF + 2 * GT_BUF)
#define SR_OFF (SL_OFF + 256)
#define SM_BYTES (SR_OFF + 64)

__device__ __forceinline__ uint32_t smem_u32(const void* p) {
    uint32_t a;
    asm("{ .reg .u64 t; cvta.to.shared.u64 t, %1; cvt.u32.u64 %0, t; }"
        : "=r"(a) : "l"(p));
    return a;
}
__device__ __forceinline__ void cp_async16(uint32_t dst, const void* src) {
    asm volatile("cp.async.cg.shared.global [%0], [%1], 16;"
                 :: "r"(dst), "l"(src) : "memory");
}
__device__ __forceinline__ void mma16816(float* d, const uint32_t* a,
                                         const uint32_t* bv) {
    asm volatile(
        "mma.sync.aligned.m16n8k16.row.col.f32.bf16.bf16.f32 "
        "{%0,%1,%2,%3}, {%4,%5,%6,%7}, {%8,%9}, {%0,%1,%2,%3};"
        : "+f"(d[0]), "+f"(d[1]), "+f"(d[2]), "+f"(d[3])
        : "r"(a[0]), "r"(a[1]), "r"(a[2]), "r"(a[3]), "r"(bv[0]), "r"(bv[1]));
}
#define LDMX4(r0, r1, r2, r3, addr) \
    asm volatile("ldmatrix.sync.aligned.m8n8.x4.shared.b16 {%0,%1,%2,%3}, [%4];" \
                 : "=r"(r0), "=r"(r1), "=r"(r2), "=r"(r3) : "r"(addr))

__global__ __launch_bounds__(256, 2) void attn_kernel(
    const float* __restrict__ x,
    const float* __restrict__ gamma_p,
    float* __restrict__ out)
{
    extern __shared__ char sm[];
    const int t = threadIdx.x;
    const int lane = t & 31;
    const int wid = t >> 5;
    const int gid = lane >> 2;
    const int tig = lane & 3;
    const int b = blockIdx.y;
    const int qBase = blockIdx.x * 64;
    const int rgA = t >> 4;
    const int cgA = t & 15;

    float* sFt = (float*)(sm + FT_OFF);
    float* sL  = (float*)(sm + SL_OFF);
    float* sR  = (float*)(sm + SR_OFF);
    const uint32_t smbase = smem_u32(sm);

    // prologue: F^T, G^T tile 0, l init, batch gmax reduce
    for (int idx = t; idx < 2048; idx += 256) {
        int k = idx >> 6, tok = idx & 63;
        sFt[k * FT_STRIDE + tok] = g_ft[(b * 32 + k) * 4096 + qBase + tok];
        ((float*)(sm + GT_OFF))[k * FT_STRIDE + tok] =
            g_gt[(b * 32 + k) * 4096 + tok];
    }
    if (t < 64) sL[t] = 0.f;
    {
        float gv = g_g2blk[b * 64 + (t & 63)];
#pragma unroll
        for (int o = 16; o > 0; o >>= 1)
            gv = fmaxf(gv, __shfl_xor_sync(0xffffffffu, gv, o));
        if (lane == 0) sR[wid] = gv;
    }
    __syncthreads();

    float gm2 = sR[0];
#pragma unroll
    for (int w = 1; w < 8; w++) gm2 = fmaxf(gm2, sR[w]);
    const float gms = sqrtf(gm2);
    float mh[4];
#pragma unroll
    for (int i = 0; i < 4; i++)
        mh[i] = sqrtf(g_fn2[b * 4096 + qBase + rgA * 4 + i]) * gms;

    float acc[16][4];
#pragma unroll
    for (int j = 0; j < 16; j++)
#pragma unroll
        for (int q = 0; q < 4; q++) acc[j][q] = 0.f;

    const int qoff = (wid & 3) * 16;
    const int coff = (wid >> 2) * 128;

    // ldmatrix lane addresses
    const uint32_t aLdm = smbase + PB_OFF +
        (qoff + ((lane & 15) >> 3) * 8 + (lane & 7)) * PB_STRIDE +
        ((lane >> 4) << 4);
    const uint32_t bLdm = smbase + HS_OFF +
        (coff + (lane & 7)) * HS_STRIDE + ((lane >> 3) << 4);

    for (int kt = 0; kt < 64; kt++) {
        __syncthreads();

        // async fill H^T tile [256 c][64 key] bf16
#pragma unroll
        for (int it = 0; it < 8; it++) {
            int idx = t + it * 256;
            int ch = idx >> 3, part = idx & 7;
            uint32_t dst = smbase + HS_OFF + ch * HS_STRIDE + part * 16;
            const __nv_bfloat16* src =
                g_ht + (size_t)(b * 256 + ch) * 4096 + kt * 64 + part * 8;
            cp_async16(dst, src);
        }
        if (kt < 63) {
#pragma unroll
            for (int it = 0; it < 2; it++) {
                int idx = t + it * 256;
                int k = idx >> 4, chunk = idx & 15;
                uint32_t dst = smbase + GT_OFF + ((kt + 1) & 1) * GT_BUF +
                               k * (FT_STRIDE * 4) + chunk * 16;
                const float* src =
                    g_gt + (size_t)(b * 32 + k) * 4096 + (kt + 1) * 64 + chunk * 4;
                cp_async16(dst, src);
            }
        }
        asm volatile("cp.async.commit_group;" ::: "memory");

        // ---- S = F.G^T via f32x2 ; P = exp(S - mhat) ----
        const float* sG = (const float*)(sm + GT_OFF + (kt & 1) * GT_BUF);
        ull pA[2][4];
#pragma unroll
        for (int ip = 0; ip < 2; ip++)
#pragma unroll
            for (int j = 0; j < 4; j++) pA[ip][j] = 0ull;

#pragma unroll 8
        for (int kk = 0; kk < 32; kk++) {
            ulonglong2 fp = *(const ulonglong2*)&sFt[kk * FT_STRIDE + rgA * 4];
            float4 g4 = *(const float4*)&sG[kk * FT_STRIDE + cgA * 4];
            ull gs0 = splat2(g4.x), gs1 = splat2(g4.y);
            ull gs2 = splat2(g4.z), gs3 = splat2(g4.w);
            fma2(pA[0][0], fp.x, gs0); fma2(pA[1][0], fp.y, gs0);
            fma2(pA[0][1], fp.x, gs1); fma2(pA[1][1], fp.y, gs1);
            fma2(pA[0][2], fp.x, gs2); fma2(pA[1][2], fp.y, gs2);
            fma2(pA[0][3], fp.x, gs3); fma2(pA[1][3], fp.y, gs3);
        }

        float p[4][4];
#pragma unroll
        for (int ip = 0; ip < 2; ip++)
#pragma unroll
            for (int j = 0; j < 4; j++) {
                float2 v = unpack2(pA[ip][j]);
                p[2 * ip][j] = v.x;
                p[2 * ip + 1][j] = v.y;
            }

        float rs[4];
#pragma unroll
        for (int i = 0; i < 4; i++) {
            p[i][0] = __expf(p[i][0] - mh[i]);
            p[i][1] = __expf(p[i][1] - mh[i]);
            p[i][2] = __expf(p[i][2] - mh[i]);
            p[i][3] = __expf(p[i][3] - mh[i]);
            rs[i] = (p[i][0] + p[i][1]) + (p[i][2] + p[i][3]);
        }
#pragma unroll
        for (int off = 1; off < 16; off <<= 1)
#pragma unroll
            for (int i = 0; i < 4; i++)
                rs[i] += __shfl_xor_sync(0xffffffffu, rs[i], off);
        if (cgA == 0) {
#pragma unroll
            for (int i = 0; i < 4; i++) sL[rgA * 4 + i] += rs[i];
        }

        // store P bf16 [64 q][64 key]
#pragma unroll
        for (int i = 0; i < 4; i++) {
            __nv_bfloat162 lo = __floats2bfloat162_rn(p[i][0], p[i][1]);
            __nv_bfloat162 hi = __floats2bfloat162_rn(p[i][2], p[i][3]);
            uint2 v;
            v.x = *(uint32_t*)&lo;
            v.y = *(uint32_t*)&hi;
            *(uint2*)(sm + PB_OFF + (rgA * 4 + i) * PB_STRIDE + cgA * 8) = v;
        }

        asm volatile("cp.async.wait_group 0;" ::: "memory");
        __syncthreads();

        // ---- MMA: warp slab 16q x 128c, 64 keys; ldmatrix fragments ----
        uint32_t a[4][4];
#pragma unroll
        for (int s = 0; s < 4; s++)
            LDMX4(a[s][0], a[s][1], a[s][2], a[s][3], aLdm + 32 * s);

#pragma unroll
        for (int j = 0; j < 16; j++) {
            uint32_t b0[4], b1[4];
            uint32_t bj = bLdm + j * (8 * HS_STRIDE);
            LDMX4(b0[0], b0[1], b0[2], b0[3], bj);
            LDMX4(b1[0], b1[1], b1[2], b1[3], bj + 64);
            mma16816(acc[j], a[0], &b0[0]);
            mma16816(acc[j], a[1], &b0[2]);
            mma16816(acc[j], a[2], &b1[0]);
            mma16816(acc[j], a[3], &b1[2]);
        }
    }
    __syncthreads();

    // ---- epilogue: out = x + gamma * O / l ----
    const float gamma = *gamma_p;
    const int r0 = qoff + gid;
    const int r1 = r0 + 8;
    const float gl0 = gamma / sL[r0];
    const float gl1 = gamma / sL[r1];
    const size_t gb0 = (size_t)(b * NTOK + qBase + r0) * CDIM + coff + tig * 2;
    const size_t gb1 = (size_t)(b * NTOK + qBase + r1) * CDIM + coff + tig * 2;

#pragma unroll
    for (int j = 0; j < 16; j++) {
        float2 xv0 = *(const float2*)&x[gb0 + j * 8];
        float2 xv1 = *(const float2*)&x[gb1 + j * 8];
        float2 o0, o1;
        o0.x = xv0.x + gl0 * acc[j][0];
        o0.y = xv0.y + gl0 * acc[j][1];
        o1.x = xv1.x + gl1 * acc[j][2];
        o1.y = xv1.y + gl1 * acc[j][3];
        *(float2*)&out[gb0 + j * 8] = o0;
        *(float2*)&out[gb1 + j * 8] = o1;
    }
}

// ---------------------------------------------------------------------------
extern "C" void kernel_launch(void* const* d_in, const int* in_sizes, int n_in,
                              void* d_out, int out_size)
{
    const float* x  = (const float*)d_in[0];
    const float* wf = (const float*)d_in[1];
    const float* wg = (const float*)d_in[2];
    const float* wh = (const float*)d_in[3];
    const float* gm = (const float*)d_in[4];
    float* out = (float*)d_out;

    cudaFuncSetAttribute(attn_kernel,
                         cudaFuncAttributeMaxDynamicSharedMemorySize,
                         SM_BYTES);

    proj_kernel<<<256, 256>>>(x, wf, wg, wh);
    attn_kernel<<<dim3(64, 4), 256, SM_BYTES>>>(x, gm, out);
}